// round 1
// baseline (speedup 1.0000x reference)
#include <cuda_runtime.h>
#include <math.h>

#define NN 512
#define C 128          // HID == EDGE_DIM
#define NODE_DIM 256
#define NUM_BINS 22
#define TI 8
#define TJ 8
#define MROWS 64       // pairs per tile
#define SH_STRIDE 130  // padded h stride (bank-conflict-free broadcast column reads)
#define NTILES ((NN/TI)*(NN/TJ))   // 4096

// ---------------- device scratch (no allocation allowed) ----------------
__device__ __align__(16) float g_n2e[NN * C];
__device__ __align__(16) float g_A[NN * C];
__device__ __align__(16) float g_B[NN * C];
__device__ __align__(16) float g_R[1023 * C];

// ---------------- f32x2 packed helpers (Blackwell FFMA2) ----------------
__device__ __forceinline__ unsigned long long pack2(float lo, float hi) {
    unsigned long long r;
    asm("mov.b64 %0, {%1,%2};" : "=l"(r) : "f"(lo), "f"(hi));
    return r;
}
__device__ __forceinline__ void fma2(unsigned long long& d, unsigned long long a, unsigned long long b) {
    asm("fma.rn.f32x2 %0, %1, %2, %0;" : "+l"(d) : "l"(a), "l"(b));
}
__device__ __forceinline__ float2 unpack2(unsigned long long v) {
    float2 f;
    asm("mov.b64 {%0,%1}, %2;" : "=f"(f.x), "=f"(f.y) : "l"(v));
    return f;
}

// ---------------- distogram bin (one-hot row index; -1 => all-zero) ----------------
__device__ __forceinline__ int bin_of(float d) {
    const float lo = 0.001f;
    const float step = (20.0f - 0.001f) / 21.0f;
    if (!(d > lo)) return -1;
    int k = (int)((d - lo) / step);
    if (k > 21) k = 21;
    if (k < 0) k = 0;
    while (k > 0 && !(d > fmaf((float)k, step, lo))) --k;
    while (k < 21 && d >= fmaf((float)(k + 1), step, lo)) ++k;
    if (!(d > fmaf((float)k, step, lo))) return -1;  // exact boundary -> one-hot all zero
    return k;
}

// ================= P1: n2e = node @ W_n2e + b =================
__global__ void k_n2e(const float* __restrict__ node,
                      const float* __restrict__ W, const float* __restrict__ b) {
    __shared__ float sN[8][NODE_DIM];
    int c = threadIdx.x;
    int r0 = blockIdx.x * 8;
    for (int idx = c; idx < 8 * NODE_DIM; idx += 128)
        sN[idx >> 8][idx & 255] = node[r0 * NODE_DIM + idx];
    __syncthreads();
    float acc[8];
#pragma unroll
    for (int r = 0; r < 8; r++) acc[r] = 0.f;
    for (int k = 0; k < NODE_DIM; k++) {
        float w = W[k * C + c];
#pragma unroll
        for (int r = 0; r < 8; r++) acc[r] = fmaf(sN[r][k], w, acc[r]);
    }
    float bb = b[c];
#pragma unroll
    for (int r = 0; r < 8; r++) g_n2e[(r0 + r) * C + c] = acc[r] + bb;
}

// ================= P2: A = n2e @ W1[0:128],  B = n2e @ W1[128:256] =================
__global__ void k_AB(const float* __restrict__ W1) {
    __shared__ float sE[8][C];
    int c = threadIdx.x;
    int r0 = blockIdx.x * 8;
    for (int idx = c; idx < 8 * C; idx += 128)
        sE[idx >> 7][idx & 127] = g_n2e[r0 * C + idx];
    __syncthreads();
    float aA[8], aB[8];
#pragma unroll
    for (int r = 0; r < 8; r++) { aA[r] = 0.f; aB[r] = 0.f; }
    for (int k = 0; k < C; k++) {
        float wA = W1[k * C + c];
        float wB = W1[(C + k) * C + c];
#pragma unroll
        for (int r = 0; r < 8; r++) {
            aA[r] = fmaf(sE[r][k], wA, aA[r]);
            aB[r] = fmaf(sE[r][k], wB, aB[r]);
        }
    }
#pragma unroll
    for (int r = 0; r < 8; r++) {
        g_A[(r0 + r) * C + c] = aA[r];
        g_B[(r0 + r) * C + c] = aB[r];
    }
}

// ================= P3: R[d] = (emb(d-511) @ W_rp + b_rp) @ W1[256:384] =================
__global__ void k_R(const float* __restrict__ Wrp, const float* __restrict__ brp,
                    const float* __restrict__ W1) {
    __shared__ float sEmb[16][C];
    __shared__ float sRp[16][C];
    int tid = threadIdx.x;
    int d0 = blockIdx.x * 16;
    for (int idx = tid; idx < 16 * 64; idx += 128) {
        int r = idx >> 6, K = idx & 63;
        int d = d0 + r;
        double rel = (double)(d - 511);
        double divv = pow(2056.0, (2.0 * (double)K) / 128.0);
        double ang = rel * 3.14159265358979323846 / divv;
        sEmb[r][K] = (float)sin(ang);
        sEmb[r][64 + K] = (float)cos(ang);
    }
    __syncthreads();
    int c = tid;
    float acc[16];
    float b0 = brp[c];
#pragma unroll
    for (int r = 0; r < 16; r++) acc[r] = b0;
    for (int k = 0; k < C; k++) {
        float w = Wrp[k * C + c];
#pragma unroll
        for (int r = 0; r < 16; r++) acc[r] = fmaf(sEmb[r][k], w, acc[r]);
    }
#pragma unroll
    for (int r = 0; r < 16; r++) sRp[r][c] = acc[r];
    __syncthreads();
#pragma unroll
    for (int r = 0; r < 16; r++) acc[r] = 0.f;
    for (int k = 0; k < C; k++) {
        float w = W1[(256 + k) * C + c];
#pragma unroll
        for (int r = 0; r < 16; r++) acc[r] = fmaf(sRp[r][k], w, acc[r]);
    }
#pragma unroll
    for (int r = 0; r < 16; r++) {
        int d = d0 + r;
        if (d < 1023) g_R[d * C + c] = acc[r];
    }
}

// ================= Main fused kernel =================
struct SM {
    float W2[C * C];
    float W3[C * C];
    float H[MROWS * SH_STRIDE];
    float A[TI * C];
    float Bv[TJ * C];
    float R[15 * C];
    float Wd[NUM_BINS * C];
    float Ws[NUM_BINS * C];
    float Fi[C], Fj[C], b1v[C], b2v[C], b3v[C], gv[C], lbv[C];
    float tIx[TI * 3], tJx[TJ * 3], sIx[TI * 3], sJx[TJ * 3];
    float flI[TI], flJ[TJ], msk[MROWS];
    int dbin[MROWS], sbin[MROWS];
};

__device__ __forceinline__ void do_gemm(const float* __restrict__ sW,
                                        const float* __restrict__ sH,
                                        int tm, int tn,
                                        unsigned long long acc[4][4]) {
#pragma unroll 8
    for (int k = 0; k < C; k++) {
        const ulonglong2* wp = (const ulonglong2*)(sW + k * C + tn * 8);
        ulonglong2 wa = wp[0];
        ulonglong2 wb = wp[1];
#pragma unroll
        for (int r = 0; r < 4; r++) {
            float a = sH[(tm * 4 + r) * SH_STRIDE + k];
            unsigned long long a2 = pack2(a, a);
            fma2(acc[r][0], a2, wa.x);
            fma2(acc[r][1], a2, wa.y);
            fma2(acc[r][2], a2, wb.x);
            fma2(acc[r][3], a2, wb.y);
        }
    }
}

__global__ void __launch_bounds__(256, 1)
k_main(const float* __restrict__ trans, const float* __restrict__ sct,
       const float* __restrict__ emask, const float* __restrict__ fmask,
       const float* __restrict__ W1, const float* __restrict__ b1,
       const float* __restrict__ W2, const float* __restrict__ b2,
       const float* __restrict__ W3, const float* __restrict__ b3,
       const float* __restrict__ lng, const float* __restrict__ lnb,
       float* __restrict__ out) {
    extern __shared__ char smraw[];
    SM* s = (SM*)smraw;
    int tid = threadIdx.x;

    // one-time loads (per persistent CTA)
    for (int idx = tid; idx < (C * C) / 4; idx += 256) {
        ((float4*)s->W2)[idx] = ((const float4*)W2)[idx];
        ((float4*)s->W3)[idx] = ((const float4*)W3)[idx];
    }
    for (int idx = tid; idx < (NUM_BINS * C) / 4; idx += 256) {
        ((float4*)s->Wd)[idx] = ((const float4*)(W1 + 384 * C))[idx];
        ((float4*)s->Ws)[idx] = ((const float4*)(W1 + 406 * C))[idx];
    }
    if (tid < C) {
        s->Fi[tid] = W1[428 * C + tid];
        s->Fj[tid] = W1[429 * C + tid];
        s->b1v[tid] = b1[tid];
        s->b2v[tid] = b2[tid];
        s->b3v[tid] = b3[tid];
        s->gv[tid] = lng[tid];
        s->lbv[tid] = lnb[tid];
    }
    __syncthreads();

    int tn = tid & 15;   // channel group (8 channels)
    int tm = tid >> 4;   // row group (4 rows)
    int cH = tid & 127;  // h1 phase channel
    int mh = tid >> 7;   // h1 phase row parity

    for (int T = blockIdx.x; T < NTILES; T += gridDim.x) {
        int ti = T >> 6, tj = T & 63;
        int i0 = ti * TI, j0 = tj * TJ;
        __syncthreads();  // previous iteration fully consumed smem

        // per-tile loads
        for (int idx = tid; idx < (TI * C) / 4; idx += 256) {
            ((float4*)s->A)[idx] = ((const float4*)(g_A + i0 * C))[idx];
            ((float4*)s->Bv)[idx] = ((const float4*)(g_B + j0 * C))[idx];
        }
        int rbase = i0 - j0 + 504;
        for (int idx = tid; idx < (15 * C) / 4; idx += 256)
            ((float4*)s->R)[idx] = ((const float4*)(g_R + rbase * C))[idx];
        if (tid < TI * 3) {
            s->tIx[tid] = trans[i0 * 3 + tid];
            s->sIx[tid] = sct[i0 * 3 + tid];
        } else if (tid < TI * 3 + TJ * 3) {
            int t = tid - TI * 3;
            s->tJx[t] = trans[j0 * 3 + t];
            s->sJx[t] = sct[j0 * 3 + t];
        }
        if (tid >= 64 && tid < 64 + TI) s->flI[tid - 64] = fmask[i0 + (tid - 64)];
        if (tid >= 80 && tid < 80 + TJ) s->flJ[tid - 80] = fmask[j0 + (tid - 80)];
        if (tid >= 128 && tid < 192) {
            int m = tid - 128;
            s->msk[m] = emask[(i0 + (m >> 3)) * NN + j0 + (m & 7)];
        }
        __syncthreads();

        // bins
        if (tid < MROWS) {
            int ii = tid >> 3, jj = tid & 7;
            float dx = s->tIx[ii * 3 + 0] - s->tJx[jj * 3 + 0];
            float dy = s->tIx[ii * 3 + 1] - s->tJx[jj * 3 + 1];
            float dz = s->tIx[ii * 3 + 2] - s->tJx[jj * 3 + 2];
            s->dbin[tid] = bin_of(sqrtf(dx * dx + dy * dy + dz * dz));
            dx = s->sIx[ii * 3 + 0] - s->sJx[jj * 3 + 0];
            dy = s->sIx[ii * 3 + 1] - s->sJx[jj * 3 + 1];
            dz = s->sIx[ii * 3 + 2] - s->sJx[jj * 3 + 2];
            s->sbin[tid] = bin_of(sqrtf(dx * dx + dy * dy + dz * dz));
        }
        __syncthreads();

        // h1 = relu(A[i]+B[j]+R[i-j]+Wd[db]+Ws[sb]+flow+b1)
#pragma unroll 4
        for (int r = 0; r < 32; r++) {
            int m = mh + 2 * r;
            int ii = m >> 3, jj = m & 7;
            float v = s->A[ii * C + cH] + s->Bv[jj * C + cH] +
                      s->R[(ii - jj + 7) * C + cH] + s->b1v[cH];
            v = fmaf(s->flI[ii], s->Fi[cH], v);
            v = fmaf(s->flJ[jj], s->Fj[cH], v);
            int db = s->dbin[m];
            if (db >= 0) v += s->Wd[db * C + cH];
            int sb = s->sbin[m];
            if (sb >= 0) v += s->Ws[sb * C + cH];
            s->H[m * SH_STRIDE + cH] = fmaxf(v, 0.f);
        }
        __syncthreads();

        // GEMM1: h2 = relu(h1 @ W2 + b2)
        unsigned long long acc[4][4];
#pragma unroll
        for (int q = 0; q < 4; q++) {
            unsigned long long bq = pack2(s->b2v[tn * 8 + 2 * q], s->b2v[tn * 8 + 2 * q + 1]);
#pragma unroll
            for (int r = 0; r < 4; r++) acc[r][q] = bq;
        }
        do_gemm(s->W2, s->H, tm, tn, acc);
        __syncthreads();  // all reads of H done
#pragma unroll
        for (int r = 0; r < 4; r++) {
            float* hrow = s->H + (tm * 4 + r) * SH_STRIDE + tn * 8;
#pragma unroll
            for (int q = 0; q < 4; q++) {
                float2 f = unpack2(acc[r][q]);
                hrow[2 * q + 0] = fmaxf(f.x, 0.f);
                hrow[2 * q + 1] = fmaxf(f.y, 0.f);
            }
        }
        __syncthreads();

        // GEMM2: h3 = h2 @ W3 + b3
#pragma unroll
        for (int q = 0; q < 4; q++) {
            unsigned long long bq = pack2(s->b3v[tn * 8 + 2 * q], s->b3v[tn * 8 + 2 * q + 1]);
#pragma unroll
            for (int r = 0; r < 4; r++) acc[r][q] = bq;
        }
        do_gemm(s->W3, s->H, tm, tn, acc);

        // LayerNorm + mask + store
#pragma unroll
        for (int r = 0; r < 4; r++) {
            int m = tm * 4 + r;
            float v[8];
#pragma unroll
            for (int q = 0; q < 4; q++) {
                float2 f = unpack2(acc[r][q]);
                v[2 * q] = f.x;
                v[2 * q + 1] = f.y;
            }
            float sum = 0.f, sq = 0.f;
#pragma unroll
            for (int q = 0; q < 8; q++) { sum += v[q]; sq += v[q] * v[q]; }
#pragma unroll
            for (int o = 1; o < 16; o <<= 1) {
                sum += __shfl_xor_sync(0xffffffffu, sum, o);
                sq += __shfl_xor_sync(0xffffffffu, sq, o);
            }
            float mu = sum * (1.0f / 128.0f);
            float var = sq * (1.0f / 128.0f) - mu * mu;
            float inv = rsqrtf(var + 1e-5f);
            float mk = s->msk[m];
            int cb = tn * 8;
            float y[8];
#pragma unroll
            for (int q = 0; q < 8; q++)
                y[q] = ((v[q] - mu) * inv * s->gv[cb + q] + s->lbv[cb + q]) * mk;
            size_t pair = (size_t)(i0 + (m >> 3)) * NN + (size_t)(j0 + (m & 7));
            float4* op = (float4*)(out + pair * C + cb);
            op[0] = make_float4(y[0], y[1], y[2], y[3]);
            op[1] = make_float4(y[4], y[5], y[6], y[7]);
        }
    }
}

// ================= launch =================
extern "C" void kernel_launch(void* const* d_in, const int* in_sizes, int n_in,
                              void* d_out, int out_size) {
    const float* node  = (const float*)d_in[0];
    const float* trans = (const float*)d_in[1];
    const float* sct   = (const float*)d_in[2];
    const float* emask = (const float*)d_in[3];
    const float* fmask = (const float*)d_in[4];
    const float* W_n2e = (const float*)d_in[5];
    const float* b_n2e = (const float*)d_in[6];
    const float* W_rp  = (const float*)d_in[7];
    const float* b_rp  = (const float*)d_in[8];
    const float* W1    = (const float*)d_in[9];
    const float* b1    = (const float*)d_in[10];
    const float* W2    = (const float*)d_in[11];
    const float* b2    = (const float*)d_in[12];
    const float* W3    = (const float*)d_in[13];
    const float* b3    = (const float*)d_in[14];
    const float* lng   = (const float*)d_in[15];
    const float* lnb   = (const float*)d_in[16];
    float* out = (float*)d_out;

    int dev = 0;
    cudaGetDevice(&dev);
    int sms = 148;
    cudaDeviceGetAttribute(&sms, cudaDevAttrMultiProcessorCount, dev);

    size_t smem = sizeof(SM);
    cudaFuncSetAttribute(k_main, cudaFuncAttributeMaxDynamicSharedMemorySize, (int)smem);

    k_n2e<<<64, 128>>>(node, W_n2e, b_n2e);
    k_AB<<<64, 128>>>(W1);
    k_R<<<64, 128>>>(W_rp, b_rp, W1);
    k_main<<<sms, 256, smem>>>(trans, sct, emask, fmask,
                               W1, b1, W2, b2, W3, b3, lng, lnb, out);
}

// round 4
// speedup vs baseline: 1.9543x; 1.9543x over previous
#include <cuda_runtime.h>
#include <cuda_bf16.h>
#include <math.h>
#include <stdint.h>

#define NN 512
#define C 128
#define NODE_DIM 256
#define TI 16
#define TJ 8
#define NTILES ((NN/TI)*(NN/TJ))   // 32*64 = 2048

// ---------------- device scratch ----------------
__device__ __align__(16) float g_n2e[NN * C];
__device__ __align__(16) float g_A[NN * C];
__device__ __align__(16) float g_B[NN * C];
__device__ __align__(16) float g_R[1023 * C];

// ---------------- smem layout (byte offsets) ----------------
#define OFF_W2HI 0
#define OFF_W2LO 32768
#define OFF_W3HI 65536
#define OFF_W3LO 98304
#define OFF_HHI  131072
#define OFF_HLO  163840
#define OFF_TBLA 196608
#define OFF_TBLB 204800
#define OFF_TBLR 208896
#define OFF_B1   220672
#define OFF_B2   221184
#define OFF_B3   221696
#define OFF_G    222208
#define OFF_LB   222720
#define OFF_FI   223232
#define OFF_FJ   223744
#define OFF_PSUM 224256
#define OFF_PSQ  225280
#define OFF_TIX  226304
#define OFF_TJX  226496
#define OFF_SIX  226592
#define OFF_SJX  226784
#define OFF_FLI  226880
#define OFF_FLJ  226944
#define OFF_DBIN 226976
#define OFF_SBIN 227488
#define SMEM_BYTES (228000 + 1024)

// swizzled byte offset inside a [rows x 128col bf16] tile (256B rows)
#define SWZ(row, bc) ((uint32_t)(row) * 256u + ((uint32_t)(bc) ^ (((uint32_t)(row) & 7u) << 4)))

// ---------------- PTX helpers ----------------
__device__ __forceinline__ uint32_t s2u(const void* p) {
    uint32_t a;
    asm("{ .reg .u64 t; cvta.to.shared.u64 t, %1; cvt.u32.u64 %0, t; }" : "=r"(a) : "l"(p));
    return a;
}
__device__ __forceinline__ void ldsm4(uint32_t* r, uint32_t addr) {
    asm volatile("ldmatrix.sync.aligned.m8n8.x4.shared.b16 {%0,%1,%2,%3}, [%4];"
                 : "=r"(r[0]), "=r"(r[1]), "=r"(r[2]), "=r"(r[3]) : "r"(addr));
}
__device__ __forceinline__ void ldsm4t(uint32_t* r, uint32_t addr) {
    asm volatile("ldmatrix.sync.aligned.m8n8.x4.trans.shared.b16 {%0,%1,%2,%3}, [%4];"
                 : "=r"(r[0]), "=r"(r[1]), "=r"(r[2]), "=r"(r[3]) : "r"(addr));
}
__device__ __forceinline__ void mma16816(float* d, const uint32_t* a, uint32_t b0, uint32_t b1) {
    asm volatile(
        "mma.sync.aligned.m16n8k16.row.col.f32.bf16.bf16.f32 "
        "{%0,%1,%2,%3},{%4,%5,%6,%7},{%8,%9},{%0,%1,%2,%3};"
        : "+f"(d[0]), "+f"(d[1]), "+f"(d[2]), "+f"(d[3])
        : "r"(a[0]), "r"(a[1]), "r"(a[2]), "r"(a[3]), "r"(b0), "r"(b1));
}

// split fp32 pair -> bf16x2 hi + bf16x2 lo
__device__ __forceinline__ void split2(float a, float b, uint32_t& hi, uint32_t& lo) {
    __nv_bfloat162 h = __floats2bfloat162_rn(a, b);
    float2 hf = __bfloat1622float2(h);
    __nv_bfloat162 l = __floats2bfloat162_rn(a - hf.x, b - hf.y);
    hi = *(uint32_t*)&h;
    lo = *(uint32_t*)&l;
}

// ---------------- distogram bin ----------------
__device__ __forceinline__ int bin_of(float d) {
    const float lo = 0.001f;
    const float step = (20.0f - 0.001f) / 21.0f;
    if (!(d > lo)) return -1;
    int k = (int)((d - lo) / step);
    if (k > 21) k = 21;
    if (k < 0) k = 0;
    while (k > 0 && !(d > fmaf((float)k, step, lo))) --k;
    while (k < 21 && d >= fmaf((float)(k + 1), step, lo)) ++k;
    if (!(d > fmaf((float)k, step, lo))) return -1;
    return k;
}

// ================= P1: n2e = node @ W_n2e + b =================
__global__ void k_n2e(const float* __restrict__ node,
                      const float* __restrict__ W, const float* __restrict__ b) {
    __shared__ float sN[8][NODE_DIM];
    int c = threadIdx.x;
    int r0 = blockIdx.x * 8;
    for (int idx = c; idx < 8 * NODE_DIM; idx += 128)
        sN[idx >> 8][idx & 255] = node[r0 * NODE_DIM + idx];
    __syncthreads();
    float acc[8];
#pragma unroll
    for (int r = 0; r < 8; r++) acc[r] = 0.f;
    for (int k = 0; k < NODE_DIM; k++) {
        float w = W[k * C + c];
#pragma unroll
        for (int r = 0; r < 8; r++) acc[r] = fmaf(sN[r][k], w, acc[r]);
    }
    float bb = b[c];
#pragma unroll
    for (int r = 0; r < 8; r++) g_n2e[(r0 + r) * C + c] = acc[r] + bb;
}

// ================= P2: A/B tables =================
__global__ void k_AB(const float* __restrict__ W1) {
    __shared__ float sE[8][C];
    int c = threadIdx.x;
    int r0 = blockIdx.x * 8;
    for (int idx = c; idx < 8 * C; idx += 128)
        sE[idx >> 7][idx & 127] = g_n2e[r0 * C + idx];
    __syncthreads();
    float aA[8], aB[8];
#pragma unroll
    for (int r = 0; r < 8; r++) { aA[r] = 0.f; aB[r] = 0.f; }
    for (int k = 0; k < C; k++) {
        float wA = W1[k * C + c];
        float wB = W1[(C + k) * C + c];
#pragma unroll
        for (int r = 0; r < 8; r++) {
            aA[r] = fmaf(sE[r][k], wA, aA[r]);
            aB[r] = fmaf(sE[r][k], wB, aB[r]);
        }
    }
#pragma unroll
    for (int r = 0; r < 8; r++) {
        g_A[(r0 + r) * C + c] = aA[r];
        g_B[(r0 + r) * C + c] = aB[r];
    }
}

// ================= P3: relpos table =================
__global__ void k_R(const float* __restrict__ Wrp, const float* __restrict__ brp,
                    const float* __restrict__ W1) {
    __shared__ float sEmb[16][C];
    __shared__ float sRp[16][C];
    int tid = threadIdx.x;
    int d0 = blockIdx.x * 16;
    for (int idx = tid; idx < 16 * 64; idx += 128) {
        int r = idx >> 6, K = idx & 63;
        int d = d0 + r;
        double rel = (double)(d - 511);
        double divv = pow(2056.0, (2.0 * (double)K) / 128.0);
        double ang = rel * 3.14159265358979323846 / divv;
        sEmb[r][K] = (float)sin(ang);
        sEmb[r][64 + K] = (float)cos(ang);
    }
    __syncthreads();
    int c = tid;
    float acc[16];
    float b0 = brp[c];
#pragma unroll
    for (int r = 0; r < 16; r++) acc[r] = b0;
    for (int k = 0; k < C; k++) {
        float w = Wrp[k * C + c];
#pragma unroll
        for (int r = 0; r < 16; r++) acc[r] = fmaf(sEmb[r][k], w, acc[r]);
    }
#pragma unroll
    for (int r = 0; r < 16; r++) sRp[r][c] = acc[r];
    __syncthreads();
#pragma unroll
    for (int r = 0; r < 16; r++) acc[r] = 0.f;
    for (int k = 0; k < C; k++) {
        float w = W1[(256 + k) * C + c];
#pragma unroll
        for (int r = 0; r < 16; r++) acc[r] = fmaf(sRp[r][k], w, acc[r]);
    }
#pragma unroll
    for (int r = 0; r < 16; r++) {
        int d = d0 + r;
        if (d < 1023) g_R[d * C + c] = acc[r];
    }
}

// ===== weight prep: fp32 [K=128][N=128] -> bf16 hi/lo, swizzled [K rows][N cols] =====
__device__ void prep_w(const float* __restrict__ W, char* sm, int offHi, int offLo, int tid) {
    float* scr = (float*)(sm + OFF_HHI);
    for (int idx = tid; idx < (C * C) / 4; idx += 256)
        ((float4*)scr)[idx] = ((const float4*)W)[idx];
    __syncthreads();
    int k = tid >> 1, nb = (tid & 1) * 64;
#pragma unroll
    for (int n8 = 0; n8 < 8; n8++) {
        int n0 = nb + n8 * 8;
        uint32_t hi[4], lo[4];
#pragma unroll
        for (int q = 0; q < 4; q++) {
            float a = scr[k * C + n0 + 2 * q];
            float b = scr[k * C + n0 + 2 * q + 1];
            split2(a, b, hi[q], lo[q]);
        }
        uint32_t o = SWZ(k, n0 * 2);
        *(uint4*)(sm + offHi + o) = make_uint4(hi[0], hi[1], hi[2], hi[3]);
        *(uint4*)(sm + offLo + o) = make_uint4(lo[0], lo[1], lo[2], lo[3]);
    }
    __syncthreads();
}

// ===== GEMM: acc[M32xN64] += (Ahi+Alo)(Bhi+Blo), drop lo*lo =====
__device__ __forceinline__ void gemm128(uint32_t aHi, uint32_t aLo, uint32_t bHi, uint32_t bLo,
                                        int mw, int nw, int lane, float acc[2][8][4]) {
    int l15 = lane & 15, lh = lane >> 4;
    uint32_t arow = (uint32_t)(mw * 32 + l15);
    uint32_t asw = (arow & 7u) << 4;
    uint32_t aoff0 = arow * 256u;
    uint32_t aoff1 = aoff0 + 16u * 256u;
    uint32_t bsw = ((uint32_t)l15 & 7u) << 4;
    uint32_t bcb = (uint32_t)(nw * 128 + lh * 16);
#pragma unroll 2
    for (int ks = 0; ks < 8; ks++) {
        uint32_t abc = ((uint32_t)(ks * 32 + lh * 16)) ^ asw;
        uint32_t ah0[4], ah1[4], al0[4], al1[4];
        ldsm4(ah0, aHi + aoff0 + abc);
        ldsm4(ah1, aHi + aoff1 + abc);
        ldsm4(al0, aLo + aoff0 + abc);
        ldsm4(al1, aLo + aoff1 + abc);
        uint32_t koff = (uint32_t)(ks * 16 + l15) * 256u;
        uint32_t bh[4][4], bl[4][4];
#pragma unroll
        for (int np = 0; np < 4; np++) {
            uint32_t bbc = (bcb + (uint32_t)np * 32u) ^ bsw;
            ldsm4t(bh[np], bHi + koff + bbc);
            ldsm4t(bl[np], bLo + koff + bbc);
        }
#pragma unroll
        for (int mt = 0; mt < 2; mt++) {
            const uint32_t* ah = mt ? ah1 : ah0;
            const uint32_t* al = mt ? al1 : al0;
#pragma unroll
            for (int np = 0; np < 4; np++) {
#pragma unroll
                for (int sub = 0; sub < 2; sub++) {
                    float* d = acc[mt][np * 2 + sub];
                    uint32_t b0 = bh[np][2 * sub], b1 = bh[np][2 * sub + 1];
                    mma16816(d, ah, b0, b1);
                    mma16816(d, al, b0, b1);
                    mma16816(d, ah, bl[np][2 * sub], bl[np][2 * sub + 1]);
                }
            }
        }
    }
}

// ================= main fused kernel =================
__global__ void __launch_bounds__(256, 1)
k_main(const float* __restrict__ trans, const float* __restrict__ sct,
       const float* __restrict__ emask, const float* __restrict__ fmask,
       const float* __restrict__ W1, const float* __restrict__ b1,
       const float* __restrict__ W2, const float* __restrict__ b2,
       const float* __restrict__ W3, const float* __restrict__ b3,
       const float* __restrict__ lng, const float* __restrict__ lnb,
       float* __restrict__ out) {
    extern __shared__ char smraw[];
    char* sm = (char*)(((uintptr_t)smraw + 1023) & ~(uintptr_t)1023);
    uint32_t sbase = s2u(sm);
    int tid = threadIdx.x;
    int lane = tid & 31, w = tid >> 5;
    int mw = w & 3, nw = w >> 2;

    // one-time: weights, small vectors
    prep_w(W2, sm, OFF_W2HI, OFF_W2LO, tid);
    prep_w(W3, sm, OFF_W3HI, OFF_W3LO, tid);
    if (tid < C) {
        ((float*)(sm + OFF_B1))[tid] = b1[tid];
        ((float*)(sm + OFF_B2))[tid] = b2[tid];
        ((float*)(sm + OFF_B3))[tid] = b3[tid];
        ((float*)(sm + OFF_G))[tid] = lng[tid];
        ((float*)(sm + OFF_LB))[tid] = lnb[tid];
        ((float*)(sm + OFF_FI))[tid] = W1[428 * C + tid];
        ((float*)(sm + OFF_FJ))[tid] = W1[429 * C + tid];
    }
    __syncthreads();

    const float* sTA = (const float*)(sm + OFF_TBLA);
    const float* sTB = (const float*)(sm + OFF_TBLB);
    const float* sTR = (const float*)(sm + OFF_TBLR);
    const float* b1s = (const float*)(sm + OFF_B1);
    const float* b2s = (const float*)(sm + OFF_B2);
    const float* b3s = (const float*)(sm + OFF_B3);
    const float* gs = (const float*)(sm + OFF_G);
    const float* lbs = (const float*)(sm + OFF_LB);
    const float* fis = (const float*)(sm + OFF_FI);
    const float* fjs = (const float*)(sm + OFF_FJ);
    float* psum = (float*)(sm + OFF_PSUM);
    float* psq = (float*)(sm + OFF_PSQ);

    for (int T = blockIdx.x; T < NTILES; T += gridDim.x) {
        int i0 = (T >> 6) * TI, j0 = (T & 63) * TJ;
        __syncthreads();  // protect smem reuse from previous iteration

        // ---- stage tables + coords ----
        for (int idx = tid; idx < 512; idx += 256)
            ((float4*)(sm + OFF_TBLA))[idx] = ((const float4*)(g_A + (size_t)i0 * C))[idx];
        if (tid < 256)
            ((float4*)(sm + OFF_TBLB))[tid] = ((const float4*)(g_B + (size_t)j0 * C))[tid];
        int rbase = i0 - j0 + 504;
        for (int idx = tid; idx < 736; idx += 256)
            ((float4*)(sm + OFF_TBLR))[idx] = ((const float4*)(g_R + (size_t)rbase * C))[idx];
        if (tid < 48) {
            ((float*)(sm + OFF_TIX))[tid] = trans[i0 * 3 + tid];
            ((float*)(sm + OFF_SIX))[tid] = sct[i0 * 3 + tid];
        } else if (tid < 72) {
            int q = tid - 48;
            ((float*)(sm + OFF_TJX))[q] = trans[j0 * 3 + q];
            ((float*)(sm + OFF_SJX))[q] = sct[j0 * 3 + q];
        } else if (tid < 88) {
            ((float*)(sm + OFF_FLI))[tid - 72] = fmask[i0 + tid - 72];
        } else if (tid < 96) {
            ((float*)(sm + OFF_FLJ))[tid - 88] = fmask[j0 + tid - 88];
        }
        __syncthreads();

        // ---- bins ----
        if (tid < 128) {
            int ii = tid >> 3, jj = tid & 7;
            const float* tI = (const float*)(sm + OFF_TIX);
            const float* tJ = (const float*)(sm + OFF_TJX);
            const float* sI = (const float*)(sm + OFF_SIX);
            const float* sJ = (const float*)(sm + OFF_SJX);
            float dx = tI[ii * 3 + 0] - tJ[jj * 3 + 0];
            float dy = tI[ii * 3 + 1] - tJ[jj * 3 + 1];
            float dz = tI[ii * 3 + 2] - tJ[jj * 3 + 2];
            ((int*)(sm + OFF_DBIN))[tid] = bin_of(sqrtf(dx * dx + dy * dy + dz * dz));
            dx = sI[ii * 3 + 0] - sJ[jj * 3 + 0];
            dy = sI[ii * 3 + 1] - sJ[jj * 3 + 1];
            dz = sI[ii * 3 + 2] - sJ[jj * 3 + 2];
            ((int*)(sm + OFF_SBIN))[tid] = bin_of(sqrtf(dx * dx + dy * dy + dz * dz));
        }
        __syncthreads();

        // ---- h1 build: one row per warp per pass (broadcast reads) ----
#pragma unroll 2
        for (int p = 0; p < 16; p++) {
            int r = w * 16 + p;
            int ii = r >> 3, jj = r & 7, dd = ii - jj + 7;
            int db = ((const int*)(sm + OFF_DBIN))[r];
            int sb = ((const int*)(sm + OFF_SBIN))[r];
            float fi = ((const float*)(sm + OFF_FLI))[ii];
            float fj = ((const float*)(sm + OFF_FLJ))[jj];
            int c4 = lane * 4;
            float4 a4 = *(const float4*)(sTA + ii * C + c4);
            float4 b4 = *(const float4*)(sTB + jj * C + c4);
            float4 r4 = *(const float4*)(sTR + dd * C + c4);
            float4 o4 = *(const float4*)(b1s + c4);
            float4 f4 = *(const float4*)(fis + c4);
            float4 g4 = *(const float4*)(fjs + c4);
            float vx = a4.x + b4.x + r4.x + o4.x + fi * f4.x + fj * g4.x;
            float vy = a4.y + b4.y + r4.y + o4.y + fi * f4.y + fj * g4.y;
            float vz = a4.z + b4.z + r4.z + o4.z + fi * f4.z + fj * g4.z;
            float vw = a4.w + b4.w + r4.w + o4.w + fi * f4.w + fj * g4.w;
            if (db >= 0) {
                float4 d4 = *(const float4*)(W1 + (size_t)(384 + db) * C + c4);
                vx += d4.x; vy += d4.y; vz += d4.z; vw += d4.w;
            }
            if (sb >= 0) {
                float4 d4 = *(const float4*)(W1 + (size_t)(406 + sb) * C + c4);
                vx += d4.x; vy += d4.y; vz += d4.z; vw += d4.w;
            }
            vx = fmaxf(vx, 0.f); vy = fmaxf(vy, 0.f);
            vz = fmaxf(vz, 0.f); vw = fmaxf(vw, 0.f);
            uint32_t h0, l0, h1r, l1r;
            split2(vx, vy, h0, l0);
            split2(vz, vw, h1r, l1r);
            uint32_t o = SWZ(r, lane * 8);
            *(uint2*)(sm + OFF_HHI + o) = make_uint2(h0, h1r);
            *(uint2*)(sm + OFF_HLO + o) = make_uint2(l0, l1r);
        }
        __syncthreads();

        // ---- GEMM1 ----
        float acc[2][8][4];
#pragma unroll
        for (int a = 0; a < 2; a++)
#pragma unroll
            for (int b = 0; b < 8; b++)
#pragma unroll
                for (int q = 0; q < 4; q++) acc[a][b][q] = 0.f;
        gemm128(sbase + OFF_HHI, sbase + OFF_HLO, sbase + OFF_W2HI, sbase + OFF_W2LO,
                mw, nw, lane, acc);
        __syncthreads();  // all GEMM1 reads of H done before overwrite

        // ---- epilogue1: h2 = relu(acc + b2) -> H tiles ----
#pragma unroll
        for (int mt = 0; mt < 2; mt++) {
#pragma unroll
            for (int half = 0; half < 2; half++) {
                int r = mw * 32 + mt * 16 + half * 8 + (lane >> 2);
                uint32_t roff = (uint32_t)r * 256u;
                uint32_t rsw = ((uint32_t)r & 7u) << 4;
#pragma unroll
                for (int nt = 0; nt < 8; nt++) {
                    int col = nw * 64 + nt * 8 + 2 * (lane & 3);
                    float2 bb = *(const float2*)(b2s + col);
                    float x = fmaxf(acc[mt][nt][2 * half] + bb.x, 0.f);
                    float y = fmaxf(acc[mt][nt][2 * half + 1] + bb.y, 0.f);
                    uint32_t hi, lo;
                    split2(x, y, hi, lo);
                    uint32_t bc = ((uint32_t)(col * 2)) ^ rsw;
                    *(uint32_t*)(sm + OFF_HHI + roff + bc) = hi;
                    *(uint32_t*)(sm + OFF_HLO + roff + bc) = lo;
                }
            }
        }
        __syncthreads();

        // ---- GEMM2 ----
#pragma unroll
        for (int a = 0; a < 2; a++)
#pragma unroll
            for (int b = 0; b < 8; b++)
#pragma unroll
                for (int q = 0; q < 4; q++) acc[a][b][q] = 0.f;
        gemm128(sbase + OFF_HHI, sbase + OFF_HLO, sbase + OFF_W3HI, sbase + OFF_W3LO,
                mw, nw, lane, acc);

        // ---- LN pass 1: partial sums ----
#pragma unroll
        for (int mt = 0; mt < 2; mt++) {
#pragma unroll
            for (int half = 0; half < 2; half++) {
                int r = mw * 32 + mt * 16 + half * 8 + (lane >> 2);
                float s = 0.f, q = 0.f;
#pragma unroll
                for (int nt = 0; nt < 8; nt++) {
                    int col = nw * 64 + nt * 8 + 2 * (lane & 3);
                    float2 bb = *(const float2*)(b3s + col);
                    float x = acc[mt][nt][2 * half] + bb.x;
                    float y = acc[mt][nt][2 * half + 1] + bb.y;
                    s += x + y;
                    q += x * x + y * y;
                }
                s += __shfl_xor_sync(0xffffffffu, s, 1);
                s += __shfl_xor_sync(0xffffffffu, s, 2);
                q += __shfl_xor_sync(0xffffffffu, q, 1);
                q += __shfl_xor_sync(0xffffffffu, q, 2);
                if ((lane & 3) == 0) {
                    psum[r * 2 + nw] = s;
                    psq[r * 2 + nw] = q;
                }
            }
        }
        __syncthreads();

        // ---- LN pass 2: normalize + mask + store ----
#pragma unroll
        for (int mt = 0; mt < 2; mt++) {
#pragma unroll
            for (int half = 0; half < 2; half++) {
                int r = mw * 32 + mt * 16 + half * 8 + (lane >> 2);
                float S = psum[r * 2] + psum[r * 2 + 1];
                float Q = psq[r * 2] + psq[r * 2 + 1];
                float mu = S * (1.0f / 128.0f);
                float inv = rsqrtf(Q * (1.0f / 128.0f) - mu * mu + 1e-5f);
                int gi = i0 + (r >> 3), gj = j0 + (r & 7);
                size_t pair = (size_t)gi * NN + (size_t)gj;
                float mk = emask[pair];
                float* op = out + pair * C;
#pragma unroll
                for (int nt = 0; nt < 8; nt++) {
                    int col = nw * 64 + nt * 8 + 2 * (lane & 3);
                    float2 bb = *(const float2*)(b3s + col);
                    float2 gg = *(const float2*)(gs + col);
                    float2 ll = *(const float2*)(lbs + col);
                    float x = acc[mt][nt][2 * half] + bb.x;
                    float y = acc[mt][nt][2 * half + 1] + bb.y;
                    float2 o2;
                    o2.x = ((x - mu) * inv * gg.x + ll.x) * mk;
                    o2.y = ((y - mu) * inv * gg.y + ll.y) * mk;
                    *(float2*)(op + col) = o2;
                }
            }
        }
    }
}

// ================= launch =================
extern "C" void kernel_launch(void* const* d_in, const int* in_sizes, int n_in,
                              void* d_out, int out_size) {
    const float* node  = (const float*)d_in[0];
    const float* trans = (const float*)d_in[1];
    const float* sct   = (const float*)d_in[2];
    const float* emask = (const float*)d_in[3];
    const float* fmask = (const float*)d_in[4];
    const float* W_n2e = (const float*)d_in[5];
    const float* b_n2e = (const float*)d_in[6];
    const float* W_rp  = (const float*)d_in[7];
    const float* b_rp  = (const float*)d_in[8];
    const float* W1    = (const float*)d_in[9];
    const float* b1    = (const float*)d_in[10];
    const float* W2    = (const float*)d_in[11];
    const float* b2    = (const float*)d_in[12];
    const float* W3    = (const float*)d_in[13];
    const float* b3    = (const float*)d_in[14];
    const float* lng   = (const float*)d_in[15];
    const float* lnb   = (const float*)d_in[16];
    float* out = (float*)d_out;

    int dev = 0;
    cudaGetDevice(&dev);
    int sms = 148;
    cudaDeviceGetAttribute(&sms, cudaDevAttrMultiProcessorCount, dev);

    cudaFuncSetAttribute(k_main, cudaFuncAttributeMaxDynamicSharedMemorySize, SMEM_BYTES);

    k_n2e<<<64, 128>>>(node, W_n2e, b_n2e);
    k_AB<<<64, 128>>>(W1);
    k_R<<<64, 128>>>(W_rp, b_rp, W1);
    k_main<<<sms, 256, SMEM_BYTES>>>(trans, sct, emask, fmask,
                                     W1, b1, W2, b2, W3, b3, lng, lnb, out);
}